// round 7
// baseline (speedup 1.0000x reference)
#include <cuda_runtime.h>
#include <stdint.h>

// CutoutColor: out[n,c,h,w] = colors[n,c] if h in [top, top+28) && w in [left, left+28)
//              else x[n,c,h,w]
// x [4096, 9, 84, 84] f32, colors [4096, 9] f32, tops/lefts [4096] i32.
//
// R6: channel-fused (one thread = one spatial float4 across all 9 channels,
// front-batched LDG.128, patch-interior read-skip, .cs streaming hints) PLUS
// an 8-sample inner loop per block: 8x fewer blocks (fewer wave transitions),
// hoisted spatial math, and cross-iteration ILP (iteration k+1 loads overlap
// iteration k stores -> sustained MLP > 9 per warp).

#define N_       4096
#define C_       9
#define H_       84
#define W_       84
#define PATCH_   28
#define W4_      (W_ / 4)      // 21
#define HW4_     (H_ * W4_)    // 1764
#define NPB_     8             // samples per block

__global__ __launch_bounds__(256)
void cutout_color_kernel(const float4* __restrict__ x,
                         const float*  __restrict__ colors,
                         const int*    __restrict__ tops,
                         const int*    __restrict__ lefts,
                         float4*       __restrict__ out)
{
    const int i = blockIdx.x * blockDim.x + threadIdx.x;  // spatial vec idx
    if (i >= HW4_) return;

    // loop-invariant spatial geometry
    const int h  = i / W4_;              // const-divisor -> mul/shift
    const int w0 = (i - h * W4_) * 4;

    const int n0 = blockIdx.y * NPB_;

    #pragma unroll 2
    for (int k = 0; k < NPB_; ++k) {
        const int n = n0 + k;

        const int top  = tops[n];        // uniform per-iter -> L1 broadcast
        const int left = lefts[n];

        const bool row_in = (h >= top) & (h < top + PATCH_);
        const int  lo = left, hi = left + PATCH_;

        const int base = n * (C_ * HW4_) + i;   // vec idx of (n, c=0, i)
        const float* __restrict__ col = colors + n * C_;

        if (row_in & (w0 >= lo) & (w0 + 3 < hi)) {
            // whole vector inside patch for every channel: pure writes
            #pragma unroll
            for (int c = 0; c < C_; ++c) {
                const float f = col[c];
                __stcs(&out[base + c * HW4_], make_float4(f, f, f, f));
            }
            continue;
        }

        // Front-batch 9 independent streaming loads, then select + store.
        float4 v[C_];
        #pragma unroll
        for (int c = 0; c < C_; ++c)
            v[c] = __ldcs(&x[base + c * HW4_]);

        if (row_in) {
            const bool m0 = (w0 + 0 >= lo) & (w0 + 0 < hi);
            const bool m1 = (w0 + 1 >= lo) & (w0 + 1 < hi);
            const bool m2 = (w0 + 2 >= lo) & (w0 + 2 < hi);
            const bool m3 = (w0 + 3 >= lo) & (w0 + 3 < hi);
            #pragma unroll
            for (int c = 0; c < C_; ++c) {
                const float f = col[c];
                if (m0) v[c].x = f;
                if (m1) v[c].y = f;
                if (m2) v[c].z = f;
                if (m3) v[c].w = f;
            }
        }

        #pragma unroll
        for (int c = 0; c < C_; ++c)
            __stcs(&out[base + c * HW4_], v[c]);
    }
}

extern "C" void kernel_launch(void* const* d_in, const int* in_sizes, int n_in,
                              void* d_out, int out_size)
{
    const float4* x      = (const float4*)d_in[0];
    const float*  colors = (const float*) d_in[1];
    const int*    tops   = (const int*)   d_in[2];
    const int*    lefts  = (const int*)   d_in[3];
    float4*       out    = (float4*)      d_out;

    dim3 block(256);
    dim3 grid((HW4_ + 255) / 256, N_ / NPB_);   // (7, 512)
    cutout_color_kernel<<<grid, block>>>(x, colors, tops, lefts, out);
}

// round 9
// speedup vs baseline: 1.0437x; 1.0437x over previous
#include <cuda_runtime.h>
#include <stdint.h>

// CutoutColor: out[n,c,h,w] = colors[n,c] if h in [top, top+28) && w in [left, left+28)
//              else x[n,c,h,w]
// x [4096, 9, 84, 84] f32, colors [4096, 9] f32, tops/lefts [4096] i32.
//
// R7: R3 structure (channel-fused: one thread = one spatial float4 across all
// 9 channels; mask computed once; 9 front-batched LDG.128; patch-interior
// read-skip; .cs streaming hints) with a flattened 1D grid over N*HW4
// vectors: 4096*1764 = 7,225,344 = 28,224 * 256 exactly -> zero tail threads,
// no bounds check (R3's per-sample 7x256 grid idled 28/1792 slots per sample).

#define N_     4096
#define C_     9
#define H_     84
#define W_     84
#define PATCH_ 28
#define W4_    (W_ / 4)      // 21
#define HW4_   (H_ * W4_)    // 1764
#define TOTAL_ (N_ * HW4_)   // 7,225,344 = 28224 * 256

__global__ __launch_bounds__(256)
void cutout_color_kernel(const float4* __restrict__ x,
                         const float*  __restrict__ colors,
                         const int*    __restrict__ tops,
                         const int*    __restrict__ lefts,
                         float4*       __restrict__ out)
{
    const int tid = blockIdx.x * blockDim.x + threadIdx.x;  // 0 .. TOTAL_-1, exact

    const int n = tid / HW4_;            // const-divisor -> mul/shift
    const int i = tid - n * HW4_;        // spatial vec idx 0..1763

    const int h  = i / W4_;              // const-divisor -> mul/shift
    const int w0 = (i - h * W4_) * 4;

    const int top  = tops[n];            // warp-uniform (<=2 samples/warp) -> L1
    const int left = lefts[n];

    const bool row_in = (h >= top) & (h < top + PATCH_);
    const int  lo = left, hi = left + PATCH_;

    // vec index of (n, c=0, i); channel stride HW4_. Max ~65.0M < 2^31.
    const int base = n * (C_ * HW4_) + i;

    const float* __restrict__ col = colors + n * C_;

    if (row_in & (w0 >= lo) & (w0 + 3 < hi)) {
        // whole vector inside the patch for every channel: pure writes
        #pragma unroll
        for (int c = 0; c < C_; ++c) {
            const float f = col[c];
            __stcs(&out[base + c * HW4_], make_float4(f, f, f, f));
        }
        return;
    }

    // Front-batch all 9 independent streaming loads (high MLP), then select+store.
    float4 v[C_];
    #pragma unroll
    for (int c = 0; c < C_; ++c)
        v[c] = __ldcs(&x[base + c * HW4_]);

    if (row_in) {
        const bool m0 = (w0 + 0 >= lo) & (w0 + 0 < hi);
        const bool m1 = (w0 + 1 >= lo) & (w0 + 1 < hi);
        const bool m2 = (w0 + 2 >= lo) & (w0 + 2 < hi);
        const bool m3 = (w0 + 3 >= lo) & (w0 + 3 < hi);
        #pragma unroll
        for (int c = 0; c < C_; ++c) {
            const float f = col[c];
            if (m0) v[c].x = f;
            if (m1) v[c].y = f;
            if (m2) v[c].z = f;
            if (m3) v[c].w = f;
        }
    }

    #pragma unroll
    for (int c = 0; c < C_; ++c)
        __stcs(&out[base + c * HW4_], v[c]);
}

extern "C" void kernel_launch(void* const* d_in, const int* in_sizes, int n_in,
                              void* d_out, int out_size)
{
    const float4* x      = (const float4*)d_in[0];
    const float*  colors = (const float*) d_in[1];
    const int*    tops   = (const int*)   d_in[2];
    const int*    lefts  = (const int*)   d_in[3];
    float4*       out    = (float4*)      d_out;

    dim3 block(256);
    dim3 grid(TOTAL_ / 256);             // 28224 blocks, exact fit
    cutout_color_kernel<<<grid, block>>>(x, colors, tops, lefts, out);
}